// round 12
// baseline (speedup 1.0000x reference)
#include <cuda_runtime.h>

// Bilateral 5x5, sigma_color = sigma_space = 1.1, reflect pad, (16,3,512,512) f32.
//
// out = sum_k w_k*s_k*p_k / sum_k w_k*s_k,  w_k = exp(-a*diff^2), a = 1/(2*1.1^2);
// the reference's two normalizations cancel. exp(-a*u), u in [0,1] is a deg-2
// Chebyshev poly.
//
// R12: 5-op taps. u = (p-c)^2 = p^2 - 2cp + c^2; p^2 is precomputed into smem
// by the loader (LDS is free: fma pipe is the saturated resource at rt=2),
// u' = fma(-2c, p, p^2) and the +c^2 term is folded into per-thread poly
// coefficients (exact algebra): w = q2*u'^2 + (2 q2 cc + q1) u' + (q2 cc^2 +
// q1 cc + q0), horizontal g folded per class. Per tap: 3 fma + add + fma.

#define H 512
#define W 512
#define NPLANES 48

#define TILE_W 64
#define TILE_H 8
#define BLK_X 32
#define BLK_Y 8
#define SM_W  68
#define SM_H  12

#define G1f 0.66151464f
#define G2f 0.19149516f

// deg-2 Chebyshev coeffs for exp(-a*u), u in [0,1]
#define Q0c 0.99969391f
#define Q1c -0.40757903f
#define Q2c 0.06969310f

typedef unsigned long long u64;

__device__ __forceinline__ u64 pk(float lo, float hi) {
    u64 r; asm("mov.b64 %0, {%1, %2};" : "=l"(r) : "f"(lo), "f"(hi)); return r;
}
__device__ __forceinline__ u64 f2add(u64 a, u64 b) {
    u64 d; asm("add.rn.f32x2 %0, %1, %2;" : "=l"(d) : "l"(a), "l"(b)); return d;
}
__device__ __forceinline__ u64 f2mul(u64 a, u64 b) {
    u64 d; asm("mul.rn.f32x2 %0, %1, %2;" : "=l"(d) : "l"(a), "l"(b)); return d;
}
__device__ __forceinline__ u64 f2fma(u64 a, u64 b, u64 c) {
    u64 d; asm("fma.rn.f32x2 %0, %1, %2, %3;" : "=l"(d) : "l"(a), "l"(b), "l"(c)); return d;
}
__device__ __forceinline__ void unpk(u64 q, float& lo, float& hi) {
    asm("mov.b64 {%0, %1}, %2;" : "=f"(lo), "=f"(hi) : "l"(q));
}

__device__ __forceinline__ int reflect_idx(int i, int n) {
    if (i < 0)  i = -i;
    if (i >= n) i = 2 * n - 2 - i;
    return i;
}

__global__ __launch_bounds__(BLK_X * BLK_Y, 5)
void bilateral_kernel(const float* __restrict__ in, float* __restrict__ out) {
    // smB[r][c] == smA[r][c+1] (shifted copies -> aligned LDS.64 for odd pairs)
    // smA2/smB2 hold p^2 with the same layout.
    __shared__ __align__(8) float smA [SM_H][SM_W];
    __shared__ __align__(8) float smB [SM_H][SM_W];
    __shared__ __align__(8) float smA2[SM_H][SM_W];
    __shared__ __align__(8) float smB2[SM_H][SM_W];

    const int tx = threadIdx.x;
    const int ty = threadIdx.y;
    const int bx = blockIdx.x * TILE_W;
    const int by = blockIdx.y * TILE_H;
    const int pbase = blockIdx.z * (H * W);    // < 2^31, 32-bit safe

    // ---- division-free cooperative tile load, with p^2 ----
    const bool interior = (bx != 0) && (bx != (W - TILE_W)) &&
                          (by != 0) && (by != (H - TILE_H));

    #define STORE_SM(r, c, v)                              \
    {                                                      \
        float v2_ = (v) * (v);                             \
        smA [r][c] = (v);                                  \
        smA2[r][c] = v2_;                                  \
        if ((c) > 0) { smB[r][(c)-1] = (v); smB2[r][(c)-1] = v2_; } \
    }

    if (interior) {
        const float* src = in + (pbase + (by - 2) * W + (bx - 2));
        #pragma unroll
        for (int rr = 0; rr < 2; rr++) {
            int r = ty + rr * BLK_Y;
            if (r < SM_H) {
                const float* sr = src + r * W;
                #pragma unroll
                for (int cc = 0; cc < 3; cc++) {
                    int c = tx + cc * BLK_X;
                    if (c < SM_W) {
                        float v = sr[c];
                        STORE_SM(r, c, v)
                    }
                }
            }
        }
    } else {
        #pragma unroll
        for (int rr = 0; rr < 2; rr++) {
            int r = ty + rr * BLK_Y;
            if (r < SM_H) {
                int gy = reflect_idx(by - 2 + r, H);
                const float* sr = in + (pbase + gy * W);
                #pragma unroll
                for (int cc = 0; cc < 3; cc++) {
                    int c = tx + cc * BLK_X;
                    if (c < SM_W) {
                        int gx = reflect_idx(bx - 2 + c, W);
                        float v = sr[gx];
                        STORE_SM(r, c, v)
                    }
                }
            }
        }
    }
    #undef STORE_SM
    __syncthreads();

    // class q2 coefficients (thread-invariant -> uniform regs)
    const u64 QA2 = pk(Q2c, Q2c);                              // g = 1
    const u64 QB2 = pk(Q2c * G1f, Q2c * G1f);                  // g = G1
    const u64 QE2 = pk(Q2c * G2f, Q2c * G2f);                  // g = G2
    const u64 GV1 = pk(G1f, G1f);
    const u64 GV2 = pk(G2f, G2f);

    const int col = 2 * tx;
    const u64 ctr = *(const u64*)&smA[ty + 2][col + 2];

    // ---- per-thread folded coefficients (exact algebra) ----
    // u_true = u' + cc, u' = p^2 - 2cp, cc = c^2
    // w = Q2 u'^2 + (2 Q2 cc + Q1) u' + ((Q2 cc + Q1) cc + Q0), then * g
    const u64 ccq = f2mul(ctr, ctr);
    const u64 m   = f2mul(ctr, pk(-2.0f, -2.0f));
    const u64 r1  = f2fma(pk(2.0f * Q2c, 2.0f * Q2c), ccq, pk(Q1c, Q1c));
    const u64 tq  = f2fma(pk(Q2c, Q2c), ccq, pk(Q1c, Q1c));
    const u64 r0  = f2fma(tq, ccq, pk(Q0c, Q0c));
    const u64 q1A = r1,              q0A = r0;
    const u64 q1B = f2mul(r1, GV1),  q0B = f2mul(r0, GV1);
    const u64 q1E = f2mul(r1, GV2),  q0E = f2mul(r0, GV2);

    u64 num, den;

    #define ROWLOAD(r)                                  \
        const float* rA = &smA [ty + (r)][col];         \
        const float* sA = &smA2[ty + (r)][col];         \
        const float* rB = &smB [ty + (r)][col];         \
        const float* sB = &smB2[ty + (r)][col];         \
        u64 p0 = *(const u64*)(rA + 0);                 \
        u64 s0 = *(const u64*)(sA + 0);                 \
        u64 p1 = *(const u64*)(rB + 0);                 \
        u64 s1 = *(const u64*)(sB + 0);                 \
        u64 p2 = *(const u64*)(rA + 2);                 \
        u64 s2 = *(const u64*)(sA + 2);                 \
        u64 p3 = *(const u64*)(rB + 2);                 \
        u64 s3 = *(const u64*)(sB + 2);                 \
        u64 p4 = *(const u64*)(rA + 4);                 \
        u64 s4 = *(const u64*)(sA + 4);

    // 5-op tap: u' = fma(m,p,p2); tt = fma(q2,u',q1'); w = fma(tt,u',q0')
    #define TAPW(P, S, K2, K1, K0, WOUT)                \
        u64 WOUT;                                       \
        {                                               \
            u64 up = f2fma(m, (P), (S));                \
            u64 tt = f2fma((K2), up, (K1));             \
            WOUT = f2fma(tt, up, (K0));                 \
        }

    // ---- center row first: direct init of num/den ----
    {
        ROWLOAD(2)
        TAPW(p0, s0, QE2, q1E, q0E, w0)
        den = w0;
        num = f2mul(w0, p0);
        TAPW(p1, s1, QB2, q1B, q0B, w1)
        den = f2add(den, w1);
        num = f2fma(w1, p1, num);
        TAPW(p2, s2, QA2, q1A, q0A, w2)
        den = f2add(den, w2);
        num = f2fma(w2, p2, num);
        TAPW(p3, s3, QB2, q1B, q0B, w3)
        den = f2add(den, w3);
        num = f2fma(w3, p3, num);
        TAPW(p4, s4, QE2, q1E, q0E, w4)
        den = f2add(den, w4);
        num = f2fma(w4, p4, num);
    }

    // ---- off-center rows: row temps + vertical-weight combine ----
    #define ROWDO(r, GV)                                \
    {                                                   \
        ROWLOAD(r)                                      \
        TAPW(p0, s0, QE2, q1E, q0E, w0)                 \
        u64 rd = w0;                                    \
        u64 rn = f2mul(w0, p0);                         \
        TAPW(p1, s1, QB2, q1B, q0B, w1)                 \
        rd = f2add(rd, w1);                             \
        rn = f2fma(w1, p1, rn);                         \
        TAPW(p2, s2, QA2, q1A, q0A, w2)                 \
        rd = f2add(rd, w2);                             \
        rn = f2fma(w2, p2, rn);                         \
        TAPW(p3, s3, QB2, q1B, q0B, w3)                 \
        rd = f2add(rd, w3);                             \
        rn = f2fma(w3, p3, rn);                         \
        TAPW(p4, s4, QE2, q1E, q0E, w4)                 \
        rd = f2add(rd, w4);                             \
        rn = f2fma(w4, p4, rn);                         \
        den = f2fma((GV), rd, den);                     \
        num = f2fma((GV), rn, num);                     \
    }

    ROWDO(0, GV2)
    ROWDO(1, GV1)
    ROWDO(3, GV1)
    ROWDO(4, GV2)

    #undef ROWDO
    #undef TAPW
    #undef ROWLOAD

    float n0, n1, d0, d1;
    unpk(num, n0, n1);
    unpk(den, d0, d1);
    float2 o;
    o.x = __fdividef(n0, d0);
    o.y = __fdividef(n1, d1);
    *(float2*)&out[pbase + (by + ty) * W + bx + col] = o;
}

extern "C" void kernel_launch(void* const* d_in, const int* in_sizes, int n_in,
                              void* d_out, int out_size) {
    const float* x = (const float*)d_in[0];
    float* y = (float*)d_out;
    dim3 block(BLK_X, BLK_Y);
    dim3 grid(W / TILE_W, H / TILE_H, NPLANES);
    bilateral_kernel<<<grid, block>>>(x, y);
}

// round 13
// speedup vs baseline: 1.3977x; 1.3977x over previous
#include <cuda_runtime.h>

// Bilateral 5x5, sigma_color = sigma_space = 1.1, reflect pad, (16,3,512,512) f32.
//
// out = sum_k w_k*s_k*p_k / sum_k w_k*s_k,  w_k = exp(-a*diff^2), a = 1/(2*1.1^2);
// the reference's two normalizations cancel. exp(-a*u), u in [0,1], is a deg-2
// Chebyshev poly. Horizontal spatial weight folded into the poly coefficients
// (3 sets); vertical weight applied once per row.
//
// R13: R9 quad body (champion, 73.2us) with the DEN accumulation path
// scalarized: den += w becomes two scalar FADDs (candidate alu-pipe ops,
// offloading the saturated fma pipe); den row-combines become scalar
// FFMA-imm (rt=1). num path stays packed f32x2.

#define H 512
#define W 512
#define NPLANES 48

#define TILE_W 64
#define TILE_H 16
#define BLK_X 32
#define BLK_Y 8
#define SM_W  68
#define SM_H  20

#define G1f 0.66151464f
#define G2f 0.19149516f

// deg-2 Chebyshev coeffs for exp(-a*u), u in [0,1]
#define Q0 0.99969391f
#define Q1 -0.40757903f
#define Q2 0.06969310f

typedef unsigned long long u64;

__device__ __forceinline__ u64 pk(float lo, float hi) {
    u64 r; asm("mov.b64 %0, {%1, %2};" : "=l"(r) : "f"(lo), "f"(hi)); return r;
}
__device__ __forceinline__ u64 f2add(u64 a, u64 b) {
    u64 d; asm("add.rn.f32x2 %0, %1, %2;" : "=l"(d) : "l"(a), "l"(b)); return d;
}
__device__ __forceinline__ u64 f2sub(u64 a, u64 b) {
    u64 d; asm("sub.rn.f32x2 %0, %1, %2;" : "=l"(d) : "l"(a), "l"(b)); return d;
}
__device__ __forceinline__ u64 f2mul(u64 a, u64 b) {
    u64 d; asm("mul.rn.f32x2 %0, %1, %2;" : "=l"(d) : "l"(a), "l"(b)); return d;
}
__device__ __forceinline__ u64 f2fma(u64 a, u64 b, u64 c) {
    u64 d; asm("fma.rn.f32x2 %0, %1, %2, %3;" : "=l"(d) : "l"(a), "l"(b), "l"(c)); return d;
}
__device__ __forceinline__ void unpk(u64 q, float& lo, float& hi) {
    asm("mov.b64 {%0, %1}, %2;" : "=f"(lo), "=f"(hi) : "l"(q));
}

__device__ __forceinline__ int reflect_idx(int i, int n) {
    if (i < 0)  i = -i;
    if (i >= n) i = 2 * n - 2 - i;
    return i;
}

__global__ __launch_bounds__(BLK_X * BLK_Y, 6)
void bilateral_kernel(const float* __restrict__ in, float* __restrict__ out) {
    // smB[r][c] == smA[r][c+1]  (shifted copy -> odd-offset pairs are aligned LDS.64)
    __shared__ __align__(8) float smA[SM_H][SM_W];
    __shared__ __align__(8) float smB[SM_H][SM_W];

    const int tx = threadIdx.x;
    const int ty = threadIdx.y;
    const int bx = blockIdx.x * TILE_W;
    const int by = blockIdx.y * TILE_H;
    const int pbase = blockIdx.z * (H * W);    // < 2^31, 32-bit safe

    // ---- division-free cooperative tile load (32-bit indexing) ----
    const bool interior = (bx != 0) && (bx != (W - TILE_W)) &&
                          (by != 0) && (by != (H - TILE_H));

    #define STORE_SM(r, c, v)                  \
    {                                          \
        smA[r][c] = (v);                       \
        if ((c) > 0) smB[r][(c) - 1] = (v);    \
    }

    if (interior) {
        const float* src = in + (pbase + (by - 2) * W + (bx - 2));
        #pragma unroll
        for (int rr = 0; rr < 3; rr++) {
            int r = ty + rr * BLK_Y;
            if (r < SM_H) {
                const float* sr = src + r * W;
                #pragma unroll
                for (int cc = 0; cc < 3; cc++) {
                    int c = tx + cc * BLK_X;
                    if (c < SM_W) {
                        float v = sr[c];
                        STORE_SM(r, c, v)
                    }
                }
            }
        }
    } else {
        #pragma unroll
        for (int rr = 0; rr < 3; rr++) {
            int r = ty + rr * BLK_Y;
            if (r < SM_H) {
                int gy = reflect_idx(by - 2 + r, H);
                const float* sr = in + (pbase + gy * W);
                #pragma unroll
                for (int cc = 0; cc < 3; cc++) {
                    int c = tx + cc * BLK_X;
                    if (c < SM_W) {
                        int gx = reflect_idx(bx - 2 + c, W);
                        float v = sr[gx];
                        STORE_SM(r, c, v)
                    }
                }
            }
        }
    }
    #undef STORE_SM
    __syncthreads();

    // horizontally-folded poly coefficient sets: coef = g * {Q2, Q1, Q0}
    const u64 A2 = pk(Q2, Q2);                          // g = 1
    const u64 A1 = pk(Q1, Q1);
    const u64 A0 = pk(Q0, Q0);
    const u64 B2 = pk(0.04610273f, 0.04610273f);        // g = G1
    const u64 B1 = pk(-0.26961989f, -0.26961989f);
    const u64 B0 = pk(0.66131215f, 0.66131215f);
    const u64 E2 = pk(0.01334589f, 0.01334589f);        // g = G2
    const u64 E1 = pk(-0.07804951f, -0.07804951f);
    const u64 E0 = pk(0.19143654f, 0.19143654f);
    const u64 GV1 = pk(G1f, G1f);
    const u64 GV2 = pk(G2f, G2f);

    const int col = 2 * tx;
    const int rb  = 2 * ty;

    const u64 ctrA = *(const u64*)&smA[rb + 2][col + 2];
    const u64 ctrB = *(const u64*)&smA[rb + 3][col + 2];

    u64 numA, numB;
    float denA0, denA1, denB0, denB1;       // scalar den path (FADD/FFMA-imm)

    #define ROWLOAD(r)                                  \
        const float* rA = &smA[rb + (r)][col];          \
        const float* rB = &smB[rb + (r)][col];          \
        u64 p0 = *(const u64*)(rA + 0);                 \
        u64 p1 = *(const u64*)(rB + 0);                 \
        u64 p2 = *(const u64*)(rA + 2);                 \
        u64 p3 = *(const u64*)(rB + 2);                 \
        u64 p4 = *(const u64*)(rA + 4);

    #define TAPW(P, K2, K1, K0, WOUT)                   \
        u64 WOUT;                                       \
        {                                               \
            u64 dd = f2sub((P), ctr);                   \
            u64 uu = f2mul(dd, dd);                     \
            u64 tt = f2fma((K2), uu, (K1));             \
            WOUT = f2fma(tt, uu, (K0));                 \
        }

    // produce row sums: rn packed, rd0/rd1 scalar
    #define ROWTAPS(CTR, RN, RD0, RD1)                  \
        u64 RN; float RD0, RD1;                         \
        {                                               \
            u64 ctr = (CTR);                            \
            float wl, wh;                               \
            TAPW(p0, E2, E1, E0, w0)                    \
            unpk(w0, wl, wh);                           \
            RD0 = wl; RD1 = wh;                         \
            RN = f2mul(w0, p0);                         \
            TAPW(p1, B2, B1, B0, w1)                    \
            unpk(w1, wl, wh);                           \
            RD0 += wl; RD1 += wh;                       \
            RN = f2fma(w1, p1, RN);                     \
            TAPW(p2, A2, A1, A0, w2)                    \
            unpk(w2, wl, wh);                           \
            RD0 += wl; RD1 += wh;                       \
            RN = f2fma(w2, p2, RN);                     \
            TAPW(p3, B2, B1, B0, w3)                    \
            unpk(w3, wl, wh);                           \
            RD0 += wl; RD1 += wh;                       \
            RN = f2fma(w3, p3, RN);                     \
            TAPW(p4, E2, E1, E0, w4)                    \
            unpk(w4, wl, wh);                           \
            RD0 += wl; RD1 += wh;                       \
            RN = f2fma(w4, p4, RN);                     \
        }

    {   // row 0: A only (vertical weight G2) — init A
        ROWLOAD(0)
        ROWTAPS(ctrA, rn, rd0, rd1)
        numA = f2mul(GV2, rn);
        denA0 = G2f * rd0;                // FMUL-imm
        denA1 = G2f * rd1;
    }
    {   // row 1: A (G1), B (G2, init)
        ROWLOAD(1)
        { ROWTAPS(ctrA, rn, rd0, rd1)
          numA = f2fma(GV1, rn, numA);
          denA0 = fmaf(G1f, rd0, denA0); denA1 = fmaf(G1f, rd1, denA1); }
        { ROWTAPS(ctrB, rn, rd0, rd1)
          numB = f2mul(GV2, rn);
          denB0 = G2f * rd0;             denB1 = G2f * rd1; }
    }
    {   // row 2: A (unit), B (G1)
        ROWLOAD(2)
        { ROWTAPS(ctrA, rn, rd0, rd1)
          numA = f2add(numA, rn);
          denA0 += rd0;                  denA1 += rd1; }
        { ROWTAPS(ctrB, rn, rd0, rd1)
          numB = f2fma(GV1, rn, numB);
          denB0 = fmaf(G1f, rd0, denB0); denB1 = fmaf(G1f, rd1, denB1); }
    }
    {   // row 3: A (G1), B (unit)
        ROWLOAD(3)
        { ROWTAPS(ctrA, rn, rd0, rd1)
          numA = f2fma(GV1, rn, numA);
          denA0 = fmaf(G1f, rd0, denA0); denA1 = fmaf(G1f, rd1, denA1); }
        { ROWTAPS(ctrB, rn, rd0, rd1)
          numB = f2add(numB, rn);
          denB0 += rd0;                  denB1 += rd1; }
    }
    {   // row 4: A (G2), B (G1)
        ROWLOAD(4)
        { ROWTAPS(ctrA, rn, rd0, rd1)
          numA = f2fma(GV2, rn, numA);
          denA0 = fmaf(G2f, rd0, denA0); denA1 = fmaf(G2f, rd1, denA1); }
        { ROWTAPS(ctrB, rn, rd0, rd1)
          numB = f2fma(GV1, rn, numB);
          denB0 = fmaf(G1f, rd0, denB0); denB1 = fmaf(G1f, rd1, denB1); }
    }
    {   // row 5: B only (G2)
        ROWLOAD(5)
        ROWTAPS(ctrB, rn, rd0, rd1)
        numB = f2fma(GV2, rn, numB);
        denB0 = fmaf(G2f, rd0, denB0);   denB1 = fmaf(G2f, rd1, denB1);
    }

    #undef ROWTAPS
    #undef TAPW
    #undef ROWLOAD

    float na0, na1, nb0, nb1;
    unpk(numA, na0, na1);
    unpk(numB, nb0, nb1);

    float2 oA, oB;
    oA.x = __fdividef(na0, denA0);
    oA.y = __fdividef(na1, denA1);
    oB.x = __fdividef(nb0, denB0);
    oB.y = __fdividef(nb1, denB1);

    float* op = out + (pbase + (by + rb) * W + bx + col);
    *(float2*)op       = oA;
    *(float2*)(op + W) = oB;
}

extern "C" void kernel_launch(void* const* d_in, const int* in_sizes, int n_in,
                              void* d_out, int out_size) {
    const float* x = (const float*)d_in[0];
    float* y = (float*)d_out;
    dim3 block(BLK_X, BLK_Y);
    dim3 grid(W / TILE_W, H / TILE_H, NPLANES);
    bilateral_kernel<<<grid, block>>>(x, y);
}

// round 14
// speedup vs baseline: 1.4697x; 1.0515x over previous
#include <cuda_runtime.h>

// Bilateral 5x5, sigma_color = sigma_space = 1.1, reflect pad, (16,3,512,512) f32.
//
// out = sum_k w_k*s_k*p_k / sum_k w_k*s_k,  w_k = exp(-a*diff^2), a = 1/(2*1.1^2);
// the reference's two normalizations cancel. exp(-a*u), u in [0,1], is a deg-2
// Chebyshev poly.
//
// R14: FULL spatial fold. The complete 2D spatial weight s = Gh*Gv takes 6
// values over the 5x5 window; each gets its own poly coefficient triple
// s*{Q2,Q1,Q0} (thread-invariant -> uniform regs). Every tap is exactly
// 6 f2 ops (sub, sqr, fma, fma, den-add, num-fma) accumulating directly
// into num/den: no row temps, no row combines.

#define H 512
#define W 512
#define NPLANES 48

#define TILE_W 64
#define TILE_H 16
#define BLK_X 32
#define BLK_Y 8
#define SM_W  68
#define SM_H  20

typedef unsigned long long u64;

__device__ __forceinline__ u64 pk(float lo, float hi) {
    u64 r; asm("mov.b64 %0, {%1, %2};" : "=l"(r) : "f"(lo), "f"(hi)); return r;
}
__device__ __forceinline__ u64 f2add(u64 a, u64 b) {
    u64 d; asm("add.rn.f32x2 %0, %1, %2;" : "=l"(d) : "l"(a), "l"(b)); return d;
}
__device__ __forceinline__ u64 f2sub(u64 a, u64 b) {
    u64 d; asm("sub.rn.f32x2 %0, %1, %2;" : "=l"(d) : "l"(a), "l"(b)); return d;
}
__device__ __forceinline__ u64 f2mul(u64 a, u64 b) {
    u64 d; asm("mul.rn.f32x2 %0, %1, %2;" : "=l"(d) : "l"(a), "l"(b)); return d;
}
__device__ __forceinline__ u64 f2fma(u64 a, u64 b, u64 c) {
    u64 d; asm("fma.rn.f32x2 %0, %1, %2, %3;" : "=l"(d) : "l"(a), "l"(b), "l"(c)); return d;
}
__device__ __forceinline__ void unpk(u64 q, float& lo, float& hi) {
    asm("mov.b64 {%0, %1}, %2;" : "=f"(lo), "=f"(hi) : "l"(q));
}

__device__ __forceinline__ int reflect_idx(int i, int n) {
    if (i < 0)  i = -i;
    if (i >= n) i = 2 * n - 2 - i;
    return i;
}

// coefficient triples s*{Q2, Q1, Q0} for the 6 spatial classes
// Q = {0.06969310, -0.40757903, 0.99969391}
// s: 1, G1=0.66151464, G2=0.19149516, G1^2=0.43760162,
//    G1*G2=0.12667670, G2^2=0.03667040
#define K0_2 0.06969310f
#define K0_1 -0.40757903f
#define K0_0 0.99969391f
#define K1_2 0.04610273f
#define K1_1 -0.26961989f
#define K1_0 0.66131215f
#define K2_2 0.01334589f
#define K2_1 -0.07804951f
#define K2_0 0.19143654f
#define K3_2 0.03049787f
#define K3_1 -0.17835732f
#define K3_0 0.43746767f
#define K4_2 0.00882849f
#define K4_1 -0.05163074f
#define K4_0 0.12663790f
#define K5_2 0.00255572f
#define K5_1 -0.01494609f
#define K5_0 0.03665918f

__global__ __launch_bounds__(BLK_X * BLK_Y, 6)
void bilateral_kernel(const float* __restrict__ in, float* __restrict__ out) {
    // smB[r][c] == smA[r][c+1]  (shifted copy -> odd-offset pairs are aligned LDS.64)
    __shared__ __align__(8) float smA[SM_H][SM_W];
    __shared__ __align__(8) float smB[SM_H][SM_W];

    const int tx = threadIdx.x;
    const int ty = threadIdx.y;
    const int bx = blockIdx.x * TILE_W;
    const int by = blockIdx.y * TILE_H;
    const int pbase = blockIdx.z * (H * W);    // < 2^31, 32-bit safe

    // ---- division-free cooperative tile load (32-bit indexing) ----
    const bool interior = (bx != 0) && (bx != (W - TILE_W)) &&
                          (by != 0) && (by != (H - TILE_H));

    #define STORE_SM(r, c, v)                  \
    {                                          \
        smA[r][c] = (v);                       \
        if ((c) > 0) smB[r][(c) - 1] = (v);    \
    }

    if (interior) {
        const float* src = in + (pbase + (by - 2) * W + (bx - 2));
        #pragma unroll
        for (int rr = 0; rr < 3; rr++) {
            int r = ty + rr * BLK_Y;
            if (r < SM_H) {
                const float* sr = src + r * W;
                #pragma unroll
                for (int cc = 0; cc < 3; cc++) {
                    int c = tx + cc * BLK_X;
                    if (c < SM_W) {
                        float v = sr[c];
                        STORE_SM(r, c, v)
                    }
                }
            }
        }
    } else {
        #pragma unroll
        for (int rr = 0; rr < 3; rr++) {
            int r = ty + rr * BLK_Y;
            if (r < SM_H) {
                int gy = reflect_idx(by - 2 + r, H);
                const float* sr = in + (pbase + gy * W);
                #pragma unroll
                for (int cc = 0; cc < 3; cc++) {
                    int c = tx + cc * BLK_X;
                    if (c < SM_W) {
                        int gx = reflect_idx(bx - 2 + c, W);
                        float v = sr[gx];
                        STORE_SM(r, c, v)
                    }
                }
            }
        }
    }
    #undef STORE_SM
    __syncthreads();

    // packed coefficient triples (thread-invariant -> uniform registers)
    const u64 C0q2 = pk(K0_2, K0_2), C0q1 = pk(K0_1, K0_1), C0q0 = pk(K0_0, K0_0);
    const u64 C1q2 = pk(K1_2, K1_2), C1q1 = pk(K1_1, K1_1), C1q0 = pk(K1_0, K1_0);
    const u64 C2q2 = pk(K2_2, K2_2), C2q1 = pk(K2_1, K2_1), C2q0 = pk(K2_0, K2_0);
    const u64 C3q2 = pk(K3_2, K3_2), C3q1 = pk(K3_1, K3_1), C3q0 = pk(K3_0, K3_0);
    const u64 C4q2 = pk(K4_2, K4_2), C4q1 = pk(K4_1, K4_1), C4q0 = pk(K4_0, K4_0);
    const u64 C5q2 = pk(K5_2, K5_2), C5q1 = pk(K5_1, K5_1), C5q0 = pk(K5_0, K5_0);

    const int col = 2 * tx;
    const int rb  = 2 * ty;

    const u64 ctrA = *(const u64*)&smA[rb + 2][col + 2];
    const u64 ctrB = *(const u64*)&smA[rb + 3][col + 2];

    u64 numA, denA, numB, denB;

    #define ROWLOAD(r)                                  \
        const float* rA = &smA[rb + (r)][col];          \
        const float* rB = &smB[rb + (r)][col];          \
        u64 p0 = *(const u64*)(rA + 0);                 \
        u64 p1 = *(const u64*)(rB + 0);                 \
        u64 p2 = *(const u64*)(rA + 2);                 \
        u64 p3 = *(const u64*)(rB + 2);                 \
        u64 p4 = *(const u64*)(rA + 4);

    #define TAPACC(P, Kc, NUM, DEN)                     \
    {                                                   \
        u64 dd = f2sub((P), ctr);                       \
        u64 uu = f2mul(dd, dd);                         \
        u64 tt = f2fma(Kc##q2, uu, Kc##q1);             \
        u64 ww = f2fma(tt, uu, Kc##q0);                 \
        DEN = f2add(DEN, ww);                           \
        NUM = f2fma(ww, (P), NUM);                      \
    }

    #define TAPINIT(P, Kc, NUM, DEN)                    \
    {                                                   \
        u64 dd = f2sub((P), ctr);                       \
        u64 uu = f2mul(dd, dd);                         \
        u64 tt = f2fma(Kc##q2, uu, Kc##q1);             \
        u64 ww = f2fma(tt, uu, Kc##q0);                 \
        DEN = ww;                                       \
        NUM = f2mul(ww, (P));                           \
    }

    // 5 taps, classes [Ka, Kb, Kc, Kb, Ka]
    #define ROW5(CTR, NUM, DEN, Ka, Kb, Kc)             \
    {                                                   \
        u64 ctr = (CTR);                                \
        TAPACC(p0, Ka, NUM, DEN)                        \
        TAPACC(p1, Kb, NUM, DEN)                        \
        TAPACC(p2, Kc, NUM, DEN)                        \
        TAPACC(p3, Kb, NUM, DEN)                        \
        TAPACC(p4, Ka, NUM, DEN)                        \
    }
    #define ROW5I(CTR, NUM, DEN, Ka, Kb, Kc)            \
    {                                                   \
        u64 ctr = (CTR);                                \
        TAPINIT(p0, Ka, NUM, DEN)                       \
        TAPACC(p1, Kb, NUM, DEN)                        \
        TAPACC(p2, Kc, NUM, DEN)                        \
        TAPACC(p3, Kb, NUM, DEN)                        \
        TAPACC(p4, Ka, NUM, DEN)                        \
    }

    // vertical-distance class rows:
    //   dv=0: [C2, C1, C0]   dv=1: [C4, C3, C1]   dv=2: [C5, C4, C2]
    { ROWLOAD(0) ROW5I(ctrA, numA, denA, C5, C4, C2) }                 // A dv=2
    { ROWLOAD(1) ROW5 (ctrA, numA, denA, C4, C3, C1)                   // A dv=1
                 ROW5I(ctrB, numB, denB, C5, C4, C2) }                 // B dv=2
    { ROWLOAD(2) ROW5 (ctrA, numA, denA, C2, C1, C0)                   // A dv=0
                 ROW5 (ctrB, numB, denB, C4, C3, C1) }                 // B dv=1
    { ROWLOAD(3) ROW5 (ctrA, numA, denA, C4, C3, C1)                   // A dv=1
                 ROW5 (ctrB, numB, denB, C2, C1, C0) }                 // B dv=0
    { ROWLOAD(4) ROW5 (ctrA, numA, denA, C5, C4, C2)                   // A dv=2
                 ROW5 (ctrB, numB, denB, C4, C3, C1) }                 // B dv=1
    { ROWLOAD(5) ROW5 (ctrB, numB, denB, C5, C4, C2) }                 // B dv=2

    #undef ROW5
    #undef ROW5I
    #undef TAPACC
    #undef TAPINIT
    #undef ROWLOAD

    float na0, na1, da0, da1, nb0, nb1, db0, db1;
    unpk(numA, na0, na1);
    unpk(denA, da0, da1);
    unpk(numB, nb0, nb1);
    unpk(denB, db0, db1);

    float2 oA, oB;
    oA.x = __fdividef(na0, da0);
    oA.y = __fdividef(na1, da1);
    oB.x = __fdividef(nb0, db0);
    oB.y = __fdividef(nb1, db1);

    float* op = out + (pbase + (by + rb) * W + bx + col);
    *(float2*)op       = oA;
    *(float2*)(op + W) = oB;
}

extern "C" void kernel_launch(void* const* d_in, const int* in_sizes, int n_in,
                              void* d_out, int out_size) {
    const float* x = (const float*)d_in[0];
    float* y = (float*)d_out;
    dim3 block(BLK_X, BLK_Y);
    dim3 grid(W / TILE_W, H / TILE_H, NPLANES);
    bilateral_kernel<<<grid, block>>>(x, y);
}

// round 15
// speedup vs baseline: 1.5720x; 1.0696x over previous
#include <cuda_runtime.h>

// Bilateral 5x5, sigma_color = sigma_space = 1.1, reflect pad, (16,3,512,512) f32.
//
// out = sum_k w_k*s_k*p_k / sum_k w_k*s_k,  w_k = exp(-a*diff^2), a = 1/(2*1.1^2);
// the reference's two normalizations cancel. exp(-a*u), u in [0,1], is a deg-2
// Chebyshev poly; the full 2D spatial weight (6 classes) is folded into per-
// class poly coefficient triples (uniform registers).
//
// R15: 8 px/thread (4 wide x 2 high). 4-wide => 16B-aligned smem bases =>
// each row's 7 u64 pair-values arrive in 4x LDS.128 (ulonglong2). Four
// independent accumulation chains per thread attack the fma-pipe bubbles.

#define H 512
#define W 512
#define NPLANES 48

#define TILE_W 128
#define TILE_H 16
#define BLK_X 32
#define BLK_Y 8
#define SM_W  132
#define SM_H  20

typedef unsigned long long u64;

__device__ __forceinline__ u64 pk(float lo, float hi) {
    u64 r; asm("mov.b64 %0, {%1, %2};" : "=l"(r) : "f"(lo), "f"(hi)); return r;
}
__device__ __forceinline__ u64 f2add(u64 a, u64 b) {
    u64 d; asm("add.rn.f32x2 %0, %1, %2;" : "=l"(d) : "l"(a), "l"(b)); return d;
}
__device__ __forceinline__ u64 f2sub(u64 a, u64 b) {
    u64 d; asm("sub.rn.f32x2 %0, %1, %2;" : "=l"(d) : "l"(a), "l"(b)); return d;
}
__device__ __forceinline__ u64 f2mul(u64 a, u64 b) {
    u64 d; asm("mul.rn.f32x2 %0, %1, %2;" : "=l"(d) : "l"(a), "l"(b)); return d;
}
__device__ __forceinline__ u64 f2fma(u64 a, u64 b, u64 c) {
    u64 d; asm("fma.rn.f32x2 %0, %1, %2, %3;" : "=l"(d) : "l"(a), "l"(b), "l"(c)); return d;
}
__device__ __forceinline__ void unpk(u64 q, float& lo, float& hi) {
    asm("mov.b64 {%0, %1}, %2;" : "=f"(lo), "=f"(hi) : "l"(q));
}

__device__ __forceinline__ int reflect_idx(int i, int n) {
    if (i < 0)  i = -i;
    if (i >= n) i = 2 * n - 2 - i;
    return i;
}

// coefficient triples s*{Q2, Q1, Q0}, Q = {0.06969310, -0.40757903, 0.99969391}
// s: 1, G1, G2, G1^2, G1*G2, G2^2 (G1=0.66151464, G2=0.19149516)
#define K0_2 0.06969310f
#define K0_1 -0.40757903f
#define K0_0 0.99969391f
#define K1_2 0.04610273f
#define K1_1 -0.26961989f
#define K1_0 0.66131215f
#define K2_2 0.01334589f
#define K2_1 -0.07804951f
#define K2_0 0.19143654f
#define K3_2 0.03049787f
#define K3_1 -0.17835732f
#define K3_0 0.43746767f
#define K4_2 0.00882849f
#define K4_1 -0.05163074f
#define K4_0 0.12663790f
#define K5_2 0.00255572f
#define K5_1 -0.01494609f
#define K5_0 0.03665918f

__global__ __launch_bounds__(BLK_X * BLK_Y, 4)
void bilateral_kernel(const float* __restrict__ in, float* __restrict__ out) {
    // smB[r][c] == smA[r][c+1] (shifted copy); both 16B-aligned so 4-wide
    // threads load rows with LDS.128.
    __shared__ __align__(16) float smA[SM_H][SM_W];
    __shared__ __align__(16) float smB[SM_H][SM_W];

    const int tx = threadIdx.x;
    const int ty = threadIdx.y;
    const int bx = blockIdx.x * TILE_W;
    const int by = blockIdx.y * TILE_H;
    const int pbase = blockIdx.z * (H * W);    // < 2^31, 32-bit safe

    // ---- division-free cooperative tile load ----
    const bool interior = (bx != 0) && (bx != (W - TILE_W)) &&
                          (by != 0) && (by != (H - TILE_H));

    #define STORE_SM(r, c, v)                  \
    {                                          \
        smA[r][c] = (v);                       \
        if ((c) > 0) smB[r][(c) - 1] = (v);    \
    }

    if (interior) {
        const float* src = in + (pbase + (by - 2) * W + (bx - 2));
        #pragma unroll
        for (int rr = 0; rr < 3; rr++) {
            int r = ty + rr * BLK_Y;
            if (r < SM_H) {
                const float* sr = src + r * W;
                #pragma unroll
                for (int cc = 0; cc < 5; cc++) {
                    int c = tx + cc * BLK_X;
                    if (c < SM_W) {
                        float v = sr[c];
                        STORE_SM(r, c, v)
                    }
                }
            }
        }
    } else {
        #pragma unroll
        for (int rr = 0; rr < 3; rr++) {
            int r = ty + rr * BLK_Y;
            if (r < SM_H) {
                int gy = reflect_idx(by - 2 + r, H);
                const float* sr = in + (pbase + gy * W);
                #pragma unroll
                for (int cc = 0; cc < 5; cc++) {
                    int c = tx + cc * BLK_X;
                    if (c < SM_W) {
                        int gx = reflect_idx(bx - 2 + c, W);
                        float v = sr[gx];
                        STORE_SM(r, c, v)
                    }
                }
            }
        }
    }
    #undef STORE_SM
    __syncthreads();

    // packed coefficient triples (thread-invariant -> uniform registers)
    const u64 C0q2 = pk(K0_2, K0_2), C0q1 = pk(K0_1, K0_1), C0q0 = pk(K0_0, K0_0);
    const u64 C1q2 = pk(K1_2, K1_2), C1q1 = pk(K1_1, K1_1), C1q0 = pk(K1_0, K1_0);
    const u64 C2q2 = pk(K2_2, K2_2), C2q1 = pk(K2_1, K2_1), C2q0 = pk(K2_0, K2_0);
    const u64 C3q2 = pk(K3_2, K3_2), C3q1 = pk(K3_1, K3_1), C3q0 = pk(K3_0, K3_0);
    const u64 C4q2 = pk(K4_2, K4_2), C4q1 = pk(K4_1, K4_1), C4q0 = pk(K4_0, K4_0);
    const u64 C5q2 = pk(K5_2, K5_2), C5q1 = pk(K5_1, K5_1), C5q0 = pk(K5_0, K5_0);

    const int col = 4 * tx;        // 16B-aligned smem base column
    const int rb  = 2 * ty;

    // centers: pixel pairs 1 = cols(col+2,col+3), 2 = cols(col+4,col+5)
    const u64 ctrA1 = *(const u64*)&smA[rb + 2][col + 2];
    const u64 ctrA2 = *(const u64*)&smA[rb + 2][col + 4];
    const u64 ctrB1 = *(const u64*)&smA[rb + 3][col + 2];
    const u64 ctrB2 = *(const u64*)&smA[rb + 3][col + 4];

    u64 nA1, dA1, nA2, dA2, nB1, dB1, nB2, dB2;

    // row fetch: 7 u64 pair-values q0..q6 via 4x LDS.128
    #define ROWLOAD(r)                                              \
        const float* rA = &smA[rb + (r)][col];                      \
        const float* rB = &smB[rb + (r)][col];                      \
        ulonglong2 a0 = *(const ulonglong2*)(rA);                   \
        ulonglong2 a4 = *(const ulonglong2*)(rA + 4);               \
        ulonglong2 b0 = *(const ulonglong2*)(rB);                   \
        ulonglong2 b4 = *(const ulonglong2*)(rB + 4);               \
        u64 q0 = a0.x, q2 = a0.y, q4 = a4.x, q6 = a4.y;             \
        u64 q1 = b0.x, q3 = b0.y, q5 = b4.x;

    #define TAPACC(P, CTR, Kc, NUM, DEN)                \
    {                                                   \
        u64 dd = f2sub((P), (CTR));                     \
        u64 uu = f2mul(dd, dd);                         \
        u64 tt = f2fma(Kc##q2, uu, Kc##q1);             \
        u64 ww = f2fma(tt, uu, Kc##q0);                 \
        DEN = f2add(DEN, ww);                           \
        NUM = f2fma(ww, (P), NUM);                      \
    }

    #define TAPINIT(P, CTR, Kc, NUM, DEN)               \
    {                                                   \
        u64 dd = f2sub((P), (CTR));                     \
        u64 uu = f2mul(dd, dd);                         \
        u64 tt = f2fma(Kc##q2, uu, Kc##q1);             \
        u64 ww = f2fma(tt, uu, Kc##q0);                 \
        DEN = ww;                                       \
        NUM = f2mul(ww, (P));                           \
    }

    // pair1 uses q0..q4, pair2 uses q2..q6; classes [Ka,Kb,Kc,Kb,Ka]
    #define ROW5_P1(CTR, NUM, DEN, Ka, Kb, Kc)          \
        TAPACC(q0, CTR, Ka, NUM, DEN)                   \
        TAPACC(q1, CTR, Kb, NUM, DEN)                   \
        TAPACC(q2, CTR, Kc, NUM, DEN)                   \
        TAPACC(q3, CTR, Kb, NUM, DEN)                   \
        TAPACC(q4, CTR, Ka, NUM, DEN)
    #define ROW5_P2(CTR, NUM, DEN, Ka, Kb, Kc)          \
        TAPACC(q2, CTR, Ka, NUM, DEN)                   \
        TAPACC(q3, CTR, Kb, NUM, DEN)                   \
        TAPACC(q4, CTR, Kc, NUM, DEN)                   \
        TAPACC(q5, CTR, Kb, NUM, DEN)                   \
        TAPACC(q6, CTR, Ka, NUM, DEN)
    #define ROW5I_P1(CTR, NUM, DEN, Ka, Kb, Kc)         \
        TAPINIT(q0, CTR, Ka, NUM, DEN)                  \
        TAPACC(q1, CTR, Kb, NUM, DEN)                   \
        TAPACC(q2, CTR, Kc, NUM, DEN)                   \
        TAPACC(q3, CTR, Kb, NUM, DEN)                   \
        TAPACC(q4, CTR, Ka, NUM, DEN)
    #define ROW5I_P2(CTR, NUM, DEN, Ka, Kb, Kc)         \
        TAPINIT(q2, CTR, Ka, NUM, DEN)                  \
        TAPACC(q3, CTR, Kb, NUM, DEN)                   \
        TAPACC(q4, CTR, Kc, NUM, DEN)                   \
        TAPACC(q5, CTR, Kb, NUM, DEN)                   \
        TAPACC(q6, CTR, Ka, NUM, DEN)

    // vertical class rows: dv=0 [C2,C1,C0]; dv=1 [C4,C3,C1]; dv=2 [C5,C4,C2]
    {   // row 0: A pixels only (dv=2) — init A chains
        ROWLOAD(0)
        ROW5I_P1(ctrA1, nA1, dA1, C5, C4, C2)
        ROW5I_P2(ctrA2, nA2, dA2, C5, C4, C2)
    }
    {   // row 1: A dv=1, B dv=2 (init B)
        ROWLOAD(1)
        ROW5_P1 (ctrA1, nA1, dA1, C4, C3, C1)
        ROW5_P2 (ctrA2, nA2, dA2, C4, C3, C1)
        ROW5I_P1(ctrB1, nB1, dB1, C5, C4, C2)
        ROW5I_P2(ctrB2, nB2, dB2, C5, C4, C2)
    }
    {   // row 2: A dv=0, B dv=1
        ROWLOAD(2)
        ROW5_P1(ctrA1, nA1, dA1, C2, C1, C0)
        ROW5_P2(ctrA2, nA2, dA2, C2, C1, C0)
        ROW5_P1(ctrB1, nB1, dB1, C4, C3, C1)
        ROW5_P2(ctrB2, nB2, dB2, C4, C3, C1)
    }
    {   // row 3: A dv=1, B dv=0
        ROWLOAD(3)
        ROW5_P1(ctrA1, nA1, dA1, C4, C3, C1)
        ROW5_P2(ctrA2, nA2, dA2, C4, C3, C1)
        ROW5_P1(ctrB1, nB1, dB1, C2, C1, C0)
        ROW5_P2(ctrB2, nB2, dB2, C2, C1, C0)
    }
    {   // row 4: A dv=2, B dv=1
        ROWLOAD(4)
        ROW5_P1(ctrA1, nA1, dA1, C5, C4, C2)
        ROW5_P2(ctrA2, nA2, dA2, C5, C4, C2)
        ROW5_P1(ctrB1, nB1, dB1, C4, C3, C1)
        ROW5_P2(ctrB2, nB2, dB2, C4, C3, C1)
    }
    {   // row 5: B only (dv=2)
        ROWLOAD(5)
        ROW5_P1(ctrB1, nB1, dB1, C5, C4, C2)
        ROW5_P2(ctrB2, nB2, dB2, C5, C4, C2)
    }

    #undef ROW5_P1
    #undef ROW5_P2
    #undef ROW5I_P1
    #undef ROW5I_P2
    #undef TAPACC
    #undef TAPINIT
    #undef ROWLOAD

    float x0, x1, y0, y1;
    float4 oA, oB;
    unpk(nA1, x0, x1); unpk(dA1, y0, y1);
    oA.x = __fdividef(x0, y0); oA.y = __fdividef(x1, y1);
    unpk(nA2, x0, x1); unpk(dA2, y0, y1);
    oA.z = __fdividef(x0, y0); oA.w = __fdividef(x1, y1);
    unpk(nB1, x0, x1); unpk(dB1, y0, y1);
    oB.x = __fdividef(x0, y0); oB.y = __fdividef(x1, y1);
    unpk(nB2, x0, x1); unpk(dB2, y0, y1);
    oB.z = __fdividef(x0, y0); oB.w = __fdividef(x1, y1);

    float* op = out + (pbase + (by + rb) * W + bx + col);
    *(float4*)op       = oA;    // 16B aligned: bx+4tx
    *(float4*)(op + W) = oB;
}

extern "C" void kernel_launch(void* const* d_in, const int* in_sizes, int n_in,
                              void* d_out, int out_size) {
    const float* x = (const float*)d_in[0];
    float* y = (float*)d_out;
    dim3 block(BLK_X, BLK_Y);
    dim3 grid(W / TILE_W, H / TILE_H, NPLANES);
    bilateral_kernel<<<grid, block>>>(x, y);
}

// round 16
// speedup vs baseline: 1.5757x; 1.0024x over previous
#include <cuda_runtime.h>

// Bilateral 5x5, sigma_color = sigma_space = 1.1, reflect pad, (16,3,512,512) f32.
//
// out = sum_k w_k*s_k*p_k / sum_k w_k*s_k,  w_k = exp(-a*diff^2), a = 1/(2*1.1^2);
// the reference's two normalizations cancel. exp(-a*u), u in [0,1], is a deg-2
// Chebyshev poly; the full 2D spatial weight (6 classes) is folded into per-
// class poly coefficient triples (uniform registers).
//
// R16: R15 (8 px/thread, LDS.128 rows, 4 chains) + exact-center tap shortcut
// (d==0 -> w=Q0 exactly: 2 ops instead of 6, x4 taps) + launch_bounds(256,5)
// (51-reg cap -> 5 CTAs/SM, occ 58%).

#define H 512
#define W 512
#define NPLANES 48

#define TILE_W 128
#define TILE_H 16
#define BLK_X 32
#define BLK_Y 8
#define SM_W  132
#define SM_H  20

typedef unsigned long long u64;

__device__ __forceinline__ u64 pk(float lo, float hi) {
    u64 r; asm("mov.b64 %0, {%1, %2};" : "=l"(r) : "f"(lo), "f"(hi)); return r;
}
__device__ __forceinline__ u64 f2add(u64 a, u64 b) {
    u64 d; asm("add.rn.f32x2 %0, %1, %2;" : "=l"(d) : "l"(a), "l"(b)); return d;
}
__device__ __forceinline__ u64 f2sub(u64 a, u64 b) {
    u64 d; asm("sub.rn.f32x2 %0, %1, %2;" : "=l"(d) : "l"(a), "l"(b)); return d;
}
__device__ __forceinline__ u64 f2mul(u64 a, u64 b) {
    u64 d; asm("mul.rn.f32x2 %0, %1, %2;" : "=l"(d) : "l"(a), "l"(b)); return d;
}
__device__ __forceinline__ u64 f2fma(u64 a, u64 b, u64 c) {
    u64 d; asm("fma.rn.f32x2 %0, %1, %2, %3;" : "=l"(d) : "l"(a), "l"(b), "l"(c)); return d;
}
__device__ __forceinline__ void unpk(u64 q, float& lo, float& hi) {
    asm("mov.b64 {%0, %1}, %2;" : "=f"(lo), "=f"(hi) : "l"(q));
}

__device__ __forceinline__ int reflect_idx(int i, int n) {
    if (i < 0)  i = -i;
    if (i >= n) i = 2 * n - 2 - i;
    return i;
}

// coefficient triples s*{Q2, Q1, Q0}, Q = {0.06969310, -0.40757903, 0.99969391}
// s: 1, G1, G2, G1^2, G1*G2, G2^2 (G1=0.66151464, G2=0.19149516)
#define K0_2 0.06969310f
#define K0_1 -0.40757903f
#define K0_0 0.99969391f
#define K1_2 0.04610273f
#define K1_1 -0.26961989f
#define K1_0 0.66131215f
#define K2_2 0.01334589f
#define K2_1 -0.07804951f
#define K2_0 0.19143654f
#define K3_2 0.03049787f
#define K3_1 -0.17835732f
#define K3_0 0.43746767f
#define K4_2 0.00882849f
#define K4_1 -0.05163074f
#define K4_0 0.12663790f
#define K5_2 0.00255572f
#define K5_1 -0.01494609f
#define K5_0 0.03665918f

__global__ __launch_bounds__(BLK_X * BLK_Y, 5)
void bilateral_kernel(const float* __restrict__ in, float* __restrict__ out) {
    // smB[r][c] == smA[r][c+1] (shifted copy); both 16B-aligned so 4-wide
    // threads load rows with LDS.128.
    __shared__ __align__(16) float smA[SM_H][SM_W];
    __shared__ __align__(16) float smB[SM_H][SM_W];

    const int tx = threadIdx.x;
    const int ty = threadIdx.y;
    const int bx = blockIdx.x * TILE_W;
    const int by = blockIdx.y * TILE_H;
    const int pbase = blockIdx.z * (H * W);    // < 2^31, 32-bit safe

    // ---- division-free cooperative tile load ----
    const bool interior = (bx != 0) && (bx != (W - TILE_W)) &&
                          (by != 0) && (by != (H - TILE_H));

    #define STORE_SM(r, c, v)                  \
    {                                          \
        smA[r][c] = (v);                       \
        if ((c) > 0) smB[r][(c) - 1] = (v);    \
    }

    if (interior) {
        const float* src = in + (pbase + (by - 2) * W + (bx - 2));
        #pragma unroll
        for (int rr = 0; rr < 3; rr++) {
            int r = ty + rr * BLK_Y;
            if (r < SM_H) {
                const float* sr = src + r * W;
                #pragma unroll
                for (int cc = 0; cc < 5; cc++) {
                    int c = tx + cc * BLK_X;
                    if (c < SM_W) {
                        float v = sr[c];
                        STORE_SM(r, c, v)
                    }
                }
            }
        }
    } else {
        #pragma unroll
        for (int rr = 0; rr < 3; rr++) {
            int r = ty + rr * BLK_Y;
            if (r < SM_H) {
                int gy = reflect_idx(by - 2 + r, H);
                const float* sr = in + (pbase + gy * W);
                #pragma unroll
                for (int cc = 0; cc < 5; cc++) {
                    int c = tx + cc * BLK_X;
                    if (c < SM_W) {
                        int gx = reflect_idx(bx - 2 + c, W);
                        float v = sr[gx];
                        STORE_SM(r, c, v)
                    }
                }
            }
        }
    }
    #undef STORE_SM
    __syncthreads();

    // packed coefficient triples (thread-invariant -> uniform registers)
    const u64 C0q2 = pk(K0_2, K0_2), C0q1 = pk(K0_1, K0_1), C0q0 = pk(K0_0, K0_0);
    const u64 C1q2 = pk(K1_2, K1_2), C1q1 = pk(K1_1, K1_1), C1q0 = pk(K1_0, K1_0);
    const u64 C2q2 = pk(K2_2, K2_2), C2q1 = pk(K2_1, K2_1), C2q0 = pk(K2_0, K2_0);
    const u64 C3q2 = pk(K3_2, K3_2), C3q1 = pk(K3_1, K3_1), C3q0 = pk(K3_0, K3_0);
    const u64 C4q2 = pk(K4_2, K4_2), C4q1 = pk(K4_1, K4_1), C4q0 = pk(K4_0, K4_0);
    const u64 C5q2 = pk(K5_2, K5_2), C5q1 = pk(K5_1, K5_1), C5q0 = pk(K5_0, K5_0);

    const int col = 4 * tx;        // 16B-aligned smem base column
    const int rb  = 2 * ty;

    // centers: pixel pairs 1 = cols(col+2,col+3), 2 = cols(col+4,col+5)
    const u64 ctrA1 = *(const u64*)&smA[rb + 2][col + 2];
    const u64 ctrA2 = *(const u64*)&smA[rb + 2][col + 4];
    const u64 ctrB1 = *(const u64*)&smA[rb + 3][col + 2];
    const u64 ctrB2 = *(const u64*)&smA[rb + 3][col + 4];

    u64 nA1, dA1, nA2, dA2, nB1, dB1, nB2, dB2;

    // row fetch: 7 u64 pair-values q0..q6 via 4x LDS.128
    #define ROWLOAD(r)                                              \
        const float* rA = &smA[rb + (r)][col];                      \
        const float* rB = &smB[rb + (r)][col];                      \
        ulonglong2 a0 = *(const ulonglong2*)(rA);                   \
        ulonglong2 a4 = *(const ulonglong2*)(rA + 4);               \
        ulonglong2 b0 = *(const ulonglong2*)(rB);                   \
        ulonglong2 b4 = *(const ulonglong2*)(rB + 4);               \
        u64 q0 = a0.x, q2 = a0.y, q4 = a4.x, q6 = a4.y;             \
        u64 q1 = b0.x, q3 = b0.y, q5 = b4.x;

    #define TAPACC(P, CTR, Kc, NUM, DEN)                \
    {                                                   \
        u64 dd = f2sub((P), (CTR));                     \
        u64 uu = f2mul(dd, dd);                         \
        u64 tt = f2fma(Kc##q2, uu, Kc##q1);             \
        u64 ww = f2fma(tt, uu, Kc##q0);                 \
        DEN = f2add(DEN, ww);                           \
        NUM = f2fma(ww, (P), NUM);                      \
    }

    #define TAPINIT(P, CTR, Kc, NUM, DEN)               \
    {                                                   \
        u64 dd = f2sub((P), (CTR));                     \
        u64 uu = f2mul(dd, dd);                         \
        u64 tt = f2fma(Kc##q2, uu, Kc##q1);             \
        u64 ww = f2fma(tt, uu, Kc##q0);                 \
        DEN = ww;                                       \
        NUM = f2mul(ww, (P));                           \
    }

    // exact-center tap: d==0 -> w = C0q0 exactly (identical numerics, 2 ops)
    #define TAPCTR(CTR, NUM, DEN)                       \
    {                                                   \
        DEN = f2add(DEN, C0q0);                         \
        NUM = f2fma(C0q0, (CTR), NUM);                  \
    }

    // pair1 uses q0..q4, pair2 uses q2..q6; classes [Ka,Kb,Kc,Kb,Ka]
    #define ROW5_P1(CTR, NUM, DEN, Ka, Kb, Kc)          \
        TAPACC(q0, CTR, Ka, NUM, DEN)                   \
        TAPACC(q1, CTR, Kb, NUM, DEN)                   \
        TAPACC(q2, CTR, Kc, NUM, DEN)                   \
        TAPACC(q3, CTR, Kb, NUM, DEN)                   \
        TAPACC(q4, CTR, Ka, NUM, DEN)
    #define ROW5_P2(CTR, NUM, DEN, Ka, Kb, Kc)          \
        TAPACC(q2, CTR, Ka, NUM, DEN)                   \
        TAPACC(q3, CTR, Kb, NUM, DEN)                   \
        TAPACC(q4, CTR, Kc, NUM, DEN)                   \
        TAPACC(q5, CTR, Kb, NUM, DEN)                   \
        TAPACC(q6, CTR, Ka, NUM, DEN)
    // dv=0 variants with the exact-center shortcut in the middle slot
    #define ROW5C_P1(CTR, NUM, DEN)                     \
        TAPACC(q0, CTR, C2, NUM, DEN)                   \
        TAPACC(q1, CTR, C1, NUM, DEN)                   \
        TAPCTR(CTR, NUM, DEN)                           \
        TAPACC(q3, CTR, C1, NUM, DEN)                   \
        TAPACC(q4, CTR, C2, NUM, DEN)
    #define ROW5C_P2(CTR, NUM, DEN)                     \
        TAPACC(q2, CTR, C2, NUM, DEN)                   \
        TAPACC(q3, CTR, C1, NUM, DEN)                   \
        TAPCTR(CTR, NUM, DEN)                           \
        TAPACC(q5, CTR, C1, NUM, DEN)                   \
        TAPACC(q6, CTR, C2, NUM, DEN)
    #define ROW5I_P1(CTR, NUM, DEN, Ka, Kb, Kc)         \
        TAPINIT(q0, CTR, Ka, NUM, DEN)                  \
        TAPACC(q1, CTR, Kb, NUM, DEN)                   \
        TAPACC(q2, CTR, Kc, NUM, DEN)                   \
        TAPACC(q3, CTR, Kb, NUM, DEN)                   \
        TAPACC(q4, CTR, Ka, NUM, DEN)
    #define ROW5I_P2(CTR, NUM, DEN, Ka, Kb, Kc)         \
        TAPINIT(q2, CTR, Ka, NUM, DEN)                  \
        TAPACC(q3, CTR, Kb, NUM, DEN)                   \
        TAPACC(q4, CTR, Kc, NUM, DEN)                   \
        TAPACC(q5, CTR, Kb, NUM, DEN)                   \
        TAPACC(q6, CTR, Ka, NUM, DEN)

    // vertical class rows: dv=0 [C2,C1,C0]; dv=1 [C4,C3,C1]; dv=2 [C5,C4,C2]
    {   // row 0: A pixels only (dv=2) — init A chains
        ROWLOAD(0)
        ROW5I_P1(ctrA1, nA1, dA1, C5, C4, C2)
        ROW5I_P2(ctrA2, nA2, dA2, C5, C4, C2)
    }
    {   // row 1: A dv=1, B dv=2 (init B)
        ROWLOAD(1)
        ROW5_P1 (ctrA1, nA1, dA1, C4, C3, C1)
        ROW5_P2 (ctrA2, nA2, dA2, C4, C3, C1)
        ROW5I_P1(ctrB1, nB1, dB1, C5, C4, C2)
        ROW5I_P2(ctrB2, nB2, dB2, C5, C4, C2)
    }
    {   // row 2: A dv=0 (center shortcut), B dv=1
        ROWLOAD(2)
        ROW5C_P1(ctrA1, nA1, dA1)
        ROW5C_P2(ctrA2, nA2, dA2)
        ROW5_P1 (ctrB1, nB1, dB1, C4, C3, C1)
        ROW5_P2 (ctrB2, nB2, dB2, C4, C3, C1)
    }
    {   // row 3: A dv=1, B dv=0 (center shortcut)
        ROWLOAD(3)
        ROW5_P1 (ctrA1, nA1, dA1, C4, C3, C1)
        ROW5_P2 (ctrA2, nA2, dA2, C4, C3, C1)
        ROW5C_P1(ctrB1, nB1, dB1)
        ROW5C_P2(ctrB2, nB2, dB2)
    }
    {   // row 4: A dv=2, B dv=1
        ROWLOAD(4)
        ROW5_P1(ctrA1, nA1, dA1, C5, C4, C2)
        ROW5_P2(ctrA2, nA2, dA2, C5, C4, C2)
        ROW5_P1(ctrB1, nB1, dB1, C4, C3, C1)
        ROW5_P2(ctrB2, nB2, dB2, C4, C3, C1)
    }
    {   // row 5: B only (dv=2)
        ROWLOAD(5)
        ROW5_P1(ctrB1, nB1, dB1, C5, C4, C2)
        ROW5_P2(ctrB2, nB2, dB2, C5, C4, C2)
    }

    #undef ROW5_P1
    #undef ROW5_P2
    #undef ROW5C_P1
    #undef ROW5C_P2
    #undef ROW5I_P1
    #undef ROW5I_P2
    #undef TAPACC
    #undef TAPINIT
    #undef TAPCTR
    #undef ROWLOAD

    float x0, x1, y0, y1;
    float4 oA, oB;
    unpk(nA1, x0, x1); unpk(dA1, y0, y1);
    oA.x = __fdividef(x0, y0); oA.y = __fdividef(x1, y1);
    unpk(nA2, x0, x1); unpk(dA2, y0, y1);
    oA.z = __fdividef(x0, y0); oA.w = __fdividef(x1, y1);
    unpk(nB1, x0, x1); unpk(dB1, y0, y1);
    oB.x = __fdividef(x0, y0); oB.y = __fdividef(x1, y1);
    unpk(nB2, x0, x1); unpk(dB2, y0, y1);
    oB.z = __fdividef(x0, y0); oB.w = __fdividef(x1, y1);

    float* op = out + (pbase + (by + rb) * W + bx + col);
    *(float4*)op       = oA;    // 16B aligned: bx+4tx
    *(float4*)(op + W) = oB;
}

extern "C" void kernel_launch(void* const* d_in, const int* in_sizes, int n_in,
                              void* d_out, int out_size) {
    const float* x = (const float*)d_in[0];
    float* y = (float*)d_out;
    dim3 block(BLK_X, BLK_Y);
    dim3 grid(W / TILE_W, H / TILE_H, NPLANES);
    bilateral_kernel<<<grid, block>>>(x, y);
}